// round 3
// baseline (speedup 1.0000x reference)
#include <cuda_runtime.h>

#define NV 576
#define MROWS 144
#define ROW_DEG 15
#define BATCH 256
#define ITERS 3
#define BPC 2                      // batch elements per CTA
#define THREADS (BPC * MROWS)      // 288
#define MAXD 16                    // padded max column degree (avg 3.75, Poisson tail safe)
#define NEDGE (MROWS * ROW_DEG)    // 2160

// Per-edge data built by prep: column id, and slot address in E_cm (c*MAXD + swizzled slot)
__device__ short g_cols[NEDGE];
__device__ short g_slot[NEDGE];

// Single-CTA prep: (1) ballot-scan H rows -> sorted column ids per row
// (matches top_k lowest-index tie-break); (2) assign each edge a distinct
// slot within its column's 16-wide padded bucket (swizzled to spread banks).
__global__ void prep_kernel(const float* __restrict__ H) {
    __shared__ int deg[NV];
    const int tid = threadIdx.x;
    const int lane = tid & 31;
    const int wid = tid >> 5;

    for (int m = wid; m < MROWS; m += 32) {
        int count = 0;
        for (int base = 0; base < NV; base += 32) {
            float v = H[m * NV + base + lane];
            unsigned ball = __ballot_sync(0xffffffffu, v != 0.0f);
            int pre = __popc(ball & ((1u << lane) - 1u));
            if (v != 0.0f) {
                int slot = count + pre;
                if (slot < ROW_DEG) g_cols[m * ROW_DEG + slot] = (short)(base + lane);
            }
            count += __popc(ball);
        }
    }
    for (int i = tid; i < NV; i += blockDim.x) deg[i] = 0;
    __syncthreads();
    for (int i = tid; i < NEDGE; i += blockDim.x) {
        int c = g_cols[i];
        int s = atomicAdd(&deg[c], 1);
        int se = (s + c) & (MAXD - 1);   // swizzle: distinct within column, spreads STS banks
        g_slot[i] = (short)(c * MAXD + se);
    }
}

__global__ __launch_bounds__(THREADS) void ldpc_kernel(
    const float* __restrict__ r,
    const float* __restrict__ alpha,
    const float* __restrict__ beta,
    float* __restrict__ out)
{
    extern __shared__ float sm[];
    float* r_s  = sm;                     // [BPC][NV]
    float* sE   = sm + BPC * NV;          // [2][BPC][NV]  ping-pong: r + column sums of E
    float* E_cm = sm + 3 * BPC * NV;      // [BPC][NV*MAXD] column-major padded E

    const int tid  = threadIdx.x;
    const int half = tid / MROWS;
    const int row  = tid - half * MROWS;
    const int b    = blockIdx.x * BPC + half;

    float alv[ITERS], bev[ITERS];
    #pragma unroll
    for (int k = 0; k < ITERS; ++k) { alv[k] = alpha[k]; bev[k] = beta[k]; }

    // Zero E_cm once (pad slots stay 0 forever; live slots overwritten each iter)
    float4* ez = (float4*)E_cm;
    #pragma unroll
    for (int i = tid; i < BPC * NV * MAXD / 4; i += THREADS)
        ez[i] = make_float4(0.f, 0.f, 0.f, 0.f);

    // Load r; sE[0] starts as r (M_j at iter 0 is just r[c])
    const float* rb = r + b * NV;
    #pragma unroll
    for (int i = row; i < NV; i += MROWS) {
        float v = rb[i];
        r_s[half * NV + i] = v;
        sE[half * NV + i]  = v;
    }

    // Per-edge indices -> registers (loop-invariant)
    int cc[ROW_DEG], sl[ROW_DEG];
    #pragma unroll
    for (int j = 0; j < ROW_DEG; ++j) {
        cc[j] = g_cols[row * ROW_DEG + j];
        sl[j] = g_slot[row * ROW_DEG + j];
    }

    float Ev[ROW_DEG];
    #pragma unroll
    for (int j = 0; j < ROW_DEG; ++j) Ev[j] = 0.0f;

    __syncthreads();

    const int ebase = half * NV * MAXD;
    int cur = 0;

    #pragma unroll
    for (int it = 0; it < ITERS; ++it) {
        // ── row (check-node) phase: registers + 15 LDS gathers + 15 STS scatters ──
        float sg[ROW_DEG];
        float min1 = 3.4e38f, min2 = 3.4e38f;
        int j1 = 0;
        float s = 1.0f;
        const float* sEc = sE + cur * BPC * NV + half * NV;

        #pragma unroll
        for (int j = 0; j < ROW_DEG; ++j) {
            float Mv = sEc[cc[j]] - Ev[j];       // r + sumE - E_j
            float g = (Mv > 0.0f) ? 1.0f : ((Mv < 0.0f) ? -1.0f : 0.0f);
            s *= g;
            float av = fabsf(Mv);
            if (av < min1) { min2 = min1; min1 = av; j1 = j; }
            else if (av < min2) { min2 = av; }
            sg[j] = g;
        }

        const float coef = alv[it] * s;
        const float m1c = fmaxf(0.0f, min1 - bev[it]);
        const float m2c = fmaxf(0.0f, min2 - bev[it]);

        #pragma unroll
        for (int j = 0; j < ROW_DEG; ++j) {
            float Ej = coef * sg[j] * ((j == j1) ? m2c : m1c);
            Ev[j] = Ej;
            E_cm[ebase + sl[j]] = Ej;
        }
        __syncthreads();

        // ── column (variable-node) phase: 4 columns/thread, 4x LDS.128 each ──
        const int nxt = cur ^ 1;
        #pragma unroll
        for (int k = 0; k < NV / MROWS; ++k) {
            int c = row + k * MROWS;
            const float4* p = (const float4*)(E_cm + ebase + c * MAXD);
            float4 a = p[0], q = p[1], u = p[2], w = p[3];
            float ssum = ((a.x + a.y) + (a.z + a.w)) + ((q.x + q.y) + (q.z + q.w))
                       + ((u.x + u.y) + (u.z + u.w)) + ((w.x + w.y) + (w.z + w.w));
            float cs = r_s[half * NV + c] + ssum;
            if (it == ITERS - 1)
                out[b * NV + c] = cs;             // out = r + sum(E_last)
            else
                sE[nxt * BPC * NV + half * NV + c] = cs;
        }
        if (it != ITERS - 1) __syncthreads();
        cur = nxt;
    }
}

extern "C" void kernel_launch(void* const* d_in, const int* in_sizes, int n_in,
                              void* d_out, int out_size)
{
    const float* r     = (const float*)d_in[0];   // [256, 576]
    const float* H     = (const float*)d_in[1];   // [144, 576]
    const float* alpha = (const float*)d_in[2];   // [3]
    const float* beta  = (const float*)d_in[3];   // [3]
    float* out = (float*)d_out;                   // [256, 576]

    const int smem = (3 * BPC * NV + BPC * NV * MAXD) * sizeof(float);  // ~87.6 KB
    static int configured = 0;
    if (!configured) {
        cudaFuncSetAttribute(ldpc_kernel, cudaFuncAttributeMaxDynamicSharedMemorySize, smem);
        configured = 1;
    }

    prep_kernel<<<1, 1024>>>(H);
    ldpc_kernel<<<BATCH / BPC, THREADS, smem>>>(r, alpha, beta, out);
}

// round 4
// speedup vs baseline: 1.9867x; 1.9867x over previous
#include <cuda_runtime.h>

#define NV 576
#define MROWS 144
#define ROW_DEG 15
#define BATCH 256
#define ITERS 3
#define BPC 2                      // batch elements per CTA
#define THREADS (BPC * MROWS)      // 288
#define MAXD 16                    // padded max column degree
#define NEDGE (MROWS * ROW_DEG)    // 2160

__device__ short g_cols[NEDGE];
__device__ short g_slot[NEDGE];

// One warp per row (parallel across 144 CTAs): ballot + prefix-popcount ->
// column ids ascending (matches top_k lowest-index tie-break).
__global__ void prep_scan(const float* __restrict__ H) {
    int m = blockIdx.x;
    int lane = threadIdx.x;
    int count = 0;
    for (int base = 0; base < NV; base += 32) {
        float v = H[m * NV + base + lane];
        unsigned ball = __ballot_sync(0xffffffffu, v != 0.0f);
        int pre = __popc(ball & ((1u << lane) - 1u));
        if (v != 0.0f) {
            int slot = count + pre;
            if (slot < ROW_DEG) g_cols[m * ROW_DEG + slot] = (short)(base + lane);
        }
        count += __popc(ball);
    }
}

// Tiny slot-assignment kernel: each edge gets a distinct slot within its
// column's 16-wide bucket (swizzled to spread STS banks).
__global__ void prep_slots() {
    __shared__ int deg[NV];
    const int tid = threadIdx.x;
    for (int i = tid; i < NV; i += blockDim.x) deg[i] = 0;
    __syncthreads();
    for (int i = tid; i < NEDGE; i += blockDim.x) {
        int c = g_cols[i];
        int s = atomicAdd(&deg[c], 1);
        int se = (s + c) & (MAXD - 1);
        g_slot[i] = (short)(c * MAXD + se);
    }
}

__global__ __launch_bounds__(THREADS) void ldpc_kernel(
    const float* __restrict__ r,
    const float* __restrict__ alpha,
    const float* __restrict__ beta,
    float* __restrict__ out)
{
    extern __shared__ float sm[];
    float* r_s  = sm;                     // [BPC][NV]
    float* sE   = sm + BPC * NV;          // [2][BPC][NV]  ping-pong: r + col sums of E
    float* E_cm = sm + 3 * BPC * NV;      // [BPC][NV*MAXD] column-major padded E

    const int tid  = threadIdx.x;
    const int half = tid / MROWS;
    const int row  = tid - half * MROWS;
    const int b    = blockIdx.x * BPC + half;

    float alv[ITERS], bev[ITERS];
    #pragma unroll
    for (int k = 0; k < ITERS; ++k) { alv[k] = alpha[k]; bev[k] = beta[k]; }

    // Zero E_cm once (pads stay 0; live slots rewritten each iteration)
    float4* ez = (float4*)E_cm;
    #pragma unroll
    for (int i = tid; i < BPC * NV * MAXD / 4; i += THREADS)
        ez[i] = make_float4(0.f, 0.f, 0.f, 0.f);

    const float* rb = r + b * NV;
    #pragma unroll
    for (int i = row; i < NV; i += MROWS) {
        float v = rb[i];
        r_s[half * NV + i] = v;
        sE[half * NV + i]  = v;
    }

    int cc[ROW_DEG], sl[ROW_DEG];
    #pragma unroll
    for (int j = 0; j < ROW_DEG; ++j) {
        cc[j] = g_cols[row * ROW_DEG + j];
        sl[j] = g_slot[row * ROW_DEG + j];
    }

    float Ev[ROW_DEG];
    #pragma unroll
    for (int j = 0; j < ROW_DEG; ++j) Ev[j] = 0.0f;

    __syncthreads();

    const int ebase = half * NV * MAXD;
    int cur = 0;

    #pragma unroll
    for (int it = 0; it < ITERS; ++it) {
        // ── check-node phase ──
        float Mv[ROW_DEG];
        const float* sEc = sE + cur * BPC * NV + half * NV;
        #pragma unroll
        for (int j = 0; j < ROW_DEG; ++j)
            Mv[j] = sEc[cc[j]] - Ev[j];          // r + sumE - E_j

        // sign parity: XOR of all sign bits (LOP tree, parallel)
        unsigned px = 0u;
        #pragma unroll
        for (int j = 0; j < ROW_DEG; ++j) px ^= __float_as_uint(Mv[j]);
        px &= 0x80000000u;

        // min1 via FMNMX tree over |Mv| (abs is a free operand modifier)
        float a0 = fminf(fabsf(Mv[0]),  fabsf(Mv[1]));
        float a1 = fminf(fabsf(Mv[2]),  fabsf(Mv[3]));
        float a2 = fminf(fabsf(Mv[4]),  fabsf(Mv[5]));
        float a3 = fminf(fabsf(Mv[6]),  fabsf(Mv[7]));
        float a4 = fminf(fabsf(Mv[8]),  fabsf(Mv[9]));
        float a5 = fminf(fabsf(Mv[10]), fabsf(Mv[11]));
        float a6 = fminf(fabsf(Mv[12]), fabsf(Mv[13]));
        float b0 = fminf(a0, a1), b1 = fminf(a2, a3);
        float b2 = fminf(a4, a5), b3 = fminf(a6, fabsf(Mv[14]));
        float m1 = fminf(fminf(b0, b1), fminf(b2, b3));

        // j1 = lowest index achieving min1 (parallel compares + ffs)
        unsigned msk = 0u;
        #pragma unroll
        for (int j = 0; j < ROW_DEG; ++j)
            msk |= (fabsf(Mv[j]) == m1) ? (1u << j) : 0u;
        const int j1 = __ffs(msk) - 1;

        // min2 = min over j != j1 (mask j1 to +inf, second tree)
        float t[ROW_DEG];
        #pragma unroll
        for (int j = 0; j < ROW_DEG; ++j)
            t[j] = (j == j1) ? 3.4e38f : fabsf(Mv[j]);
        float c0 = fminf(t[0], t[1]),  c1 = fminf(t[2], t[3]);
        float c2 = fminf(t[4], t[5]),  c3 = fminf(t[6], t[7]);
        float c4 = fminf(t[8], t[9]),  c5 = fminf(t[10], t[11]);
        float c6 = fminf(t[12], t[13]);
        float d0 = fminf(c0, c1), d1 = fminf(c2, c3);
        float d2 = fminf(c4, c5), d3 = fminf(c6, t[14]);
        float m2 = fminf(fminf(d0, d1), fminf(d2, d3));

        // zero anywhere in the row (sign(0)=0) <=> m1 == 0 -> all E = 0
        const float zal = (m1 == 0.0f) ? 0.0f : alv[it];
        const float m1c = fmaxf(0.0f, m1 - bev[it]) * zal;
        const float m2c = fmaxf(0.0f, m2 - bev[it]) * zal;

        #pragma unroll
        for (int j = 0; j < ROW_DEG; ++j) {
            float mag = (j == j1) ? m2c : m1c;
            unsigned sb = (px ^ __float_as_uint(Mv[j])) & 0x80000000u;
            float Ej = __uint_as_float(__float_as_uint(mag) ^ sb);
            Ev[j] = Ej;
            E_cm[ebase + sl[j]] = Ej;
        }
        __syncthreads();

        // ── variable-node phase: 4 columns/thread, 4x LDS.128 each ──
        const int nxt = cur ^ 1;
        #pragma unroll
        for (int k = 0; k < NV / MROWS; ++k) {
            int c = row + k * MROWS;
            const float4* p = (const float4*)(E_cm + ebase + c * MAXD);
            float4 x = p[0], y = p[1], u = p[2], w = p[3];
            float ssum = ((x.x + x.y) + (x.z + x.w)) + ((y.x + y.y) + (y.z + y.w))
                       + ((u.x + u.y) + (u.z + u.w)) + ((w.x + w.y) + (w.z + w.w));
            float cs = r_s[half * NV + c] + ssum;
            if (it == ITERS - 1)
                out[b * NV + c] = cs;
            else
                sE[nxt * BPC * NV + half * NV + c] = cs;
        }
        if (it != ITERS - 1) __syncthreads();
        cur = nxt;
    }
}

extern "C" void kernel_launch(void* const* d_in, const int* in_sizes, int n_in,
                              void* d_out, int out_size)
{
    const float* r     = (const float*)d_in[0];   // [256, 576]
    const float* H     = (const float*)d_in[1];   // [144, 576]
    const float* alpha = (const float*)d_in[2];   // [3]
    const float* beta  = (const float*)d_in[3];   // [3]
    float* out = (float*)d_out;                   // [256, 576]

    const int smem = (3 * BPC * NV + BPC * NV * MAXD) * sizeof(float);  // ~87.6 KB
    cudaFuncSetAttribute(ldpc_kernel, cudaFuncAttributeMaxDynamicSharedMemorySize, smem);

    prep_scan<<<MROWS, 32>>>(H);
    prep_slots<<<1, 512>>>();
    ldpc_kernel<<<BATCH / BPC, THREADS, smem>>>(r, alpha, beta, out);
}

// round 5
// speedup vs baseline: 2.2272x; 1.1210x over previous
#include <cuda_runtime.h>

#define NV 576
#define MROWS 144
#define ROW_DEG 15
#define BATCH 256
#define ITERS 3
#define BPC 2                      // batch elements per CTA
#define THREADS (BPC * MROWS)      // 288
#define MAXD 16                    // padded max column degree
#define NEDGE (MROWS * ROW_DEG)

// Packed per-edge descriptor: (E_cm offset << 16) | column. Row-padded to 16
// entries (64B) so the decoder loads each row's edges with 4x LDG.128.
__device__ int g_edge[MROWS * 16];
// Monotone per-column counters for slot assignment. Never reset: slots for one
// call are a consecutive range of the counter, and (s + c) & 15 is distinct
// within a column as long as column degree <= 16 regardless of the base value.
__device__ unsigned g_cnt[NV];

// One CTA per check row, one thread per column: single parallel LDG round,
// ballot + cross-warp prefix -> edge position j (columns ascending, matching
// top_k's lowest-index tie-break), then a global atomic gives the column slot.
__global__ __launch_bounds__(NV) void prep_kernel(const float* __restrict__ H) {
    __shared__ int wcnt[NV / 32];
    const int m = blockIdx.x;
    const int t = threadIdx.x;
    const int lane = t & 31;
    const int w = t >> 5;

    float v = H[m * NV + t];
    unsigned ball = __ballot_sync(0xffffffffu, v != 0.0f);
    if (lane == 0) wcnt[w] = __popc(ball);
    __syncthreads();

    int pre = __popc(ball & ((1u << lane) - 1u));
    #pragma unroll
    for (int k = 0; k < NV / 32; ++k)
        pre += (k < w) ? wcnt[k] : 0;

    if (v != 0.0f) {
        unsigned s = atomicAdd(&g_cnt[t], 1u);
        int se = (int)((s + (unsigned)t) & (MAXD - 1u));
        int off = t * MAXD + se;                 // < 9216, fits in 16 bits
        g_edge[m * 16 + pre] = (off << 16) | t;
    }
}

__global__ __launch_bounds__(THREADS) void ldpc_kernel(
    const float* __restrict__ r,
    const float* __restrict__ alpha,
    const float* __restrict__ beta,
    float* __restrict__ out)
{
    extern __shared__ float sm[];
    float* r_s  = sm;                     // [BPC][NV]
    float* sE   = sm + BPC * NV;          // [2][BPC][NV]  ping-pong: r + col sums of E
    float* E_cm = sm + 3 * BPC * NV;      // [BPC][NV*MAXD] column-major padded E

    const int tid  = threadIdx.x;
    const int half = tid / MROWS;
    const int row  = tid - half * MROWS;
    const int b    = blockIdx.x * BPC + half;

    float alv[ITERS], bev[ITERS];
    #pragma unroll
    for (int k = 0; k < ITERS; ++k) { alv[k] = alpha[k]; bev[k] = beta[k]; }

    // Zero E_cm once (pads stay 0; live slots rewritten each iteration)
    float4* ez = (float4*)E_cm;
    #pragma unroll
    for (int i = tid; i < BPC * NV * MAXD / 4; i += THREADS)
        ez[i] = make_float4(0.f, 0.f, 0.f, 0.f);

    const float* rb = r + b * NV;
    #pragma unroll
    for (int i = row; i < NV; i += MROWS) {
        float v = rb[i];
        r_s[half * NV + i] = v;
        sE[half * NV + i]  = v;
    }

    // Packed edges: 4x LDG.128
    int cc[ROW_DEG], sl[ROW_DEG];
    {
        const int4* ep = (const int4*)(g_edge + row * 16);
        int e[16];
        #pragma unroll
        for (int q = 0; q < 4; ++q) {
            int4 x = ep[q];
            e[q * 4 + 0] = x.x; e[q * 4 + 1] = x.y;
            e[q * 4 + 2] = x.z; e[q * 4 + 3] = x.w;
        }
        #pragma unroll
        for (int j = 0; j < ROW_DEG; ++j) {
            cc[j] = e[j] & 0xFFFF;
            sl[j] = ((unsigned)e[j]) >> 16;
        }
    }

    float Ev[ROW_DEG];
    #pragma unroll
    for (int j = 0; j < ROW_DEG; ++j) Ev[j] = 0.0f;

    __syncthreads();

    const int ebase = half * NV * MAXD;
    int cur = 0;

    #pragma unroll
    for (int it = 0; it < ITERS; ++it) {
        // ── check-node phase ──
        float Mv[ROW_DEG];
        const float* sEc = sE + cur * BPC * NV + half * NV;
        #pragma unroll
        for (int j = 0; j < ROW_DEG; ++j)
            Mv[j] = sEc[cc[j]] - Ev[j];          // r + sumE - E_j

        // sign parity: XOR of sign bits (parallel LOP tree)
        unsigned px = 0u;
        #pragma unroll
        for (int j = 0; j < ROW_DEG; ++j) px ^= __float_as_uint(Mv[j]);
        px &= 0x80000000u;

        // min1 via FMNMX tree over |Mv|
        float a0 = fminf(fabsf(Mv[0]),  fabsf(Mv[1]));
        float a1 = fminf(fabsf(Mv[2]),  fabsf(Mv[3]));
        float a2 = fminf(fabsf(Mv[4]),  fabsf(Mv[5]));
        float a3 = fminf(fabsf(Mv[6]),  fabsf(Mv[7]));
        float a4 = fminf(fabsf(Mv[8]),  fabsf(Mv[9]));
        float a5 = fminf(fabsf(Mv[10]), fabsf(Mv[11]));
        float a6 = fminf(fabsf(Mv[12]), fabsf(Mv[13]));
        float b0 = fminf(a0, a1), b1 = fminf(a2, a3);
        float b2 = fminf(a4, a5), b3 = fminf(a6, fabsf(Mv[14]));
        float m1 = fminf(fminf(b0, b1), fminf(b2, b3));

        // j1 = lowest index achieving min1
        unsigned msk = 0u;
        #pragma unroll
        for (int j = 0; j < ROW_DEG; ++j)
            msk |= (fabsf(Mv[j]) == m1) ? (1u << j) : 0u;
        const int j1 = __ffs(msk) - 1;

        // min2 = min over j != j1
        float t[ROW_DEG];
        #pragma unroll
        for (int j = 0; j < ROW_DEG; ++j)
            t[j] = (j == j1) ? 3.4e38f : fabsf(Mv[j]);
        float c0 = fminf(t[0], t[1]),  c1 = fminf(t[2], t[3]);
        float c2 = fminf(t[4], t[5]),  c3 = fminf(t[6], t[7]);
        float c4 = fminf(t[8], t[9]),  c5 = fminf(t[10], t[11]);
        float c6 = fminf(t[12], t[13]);
        float d0 = fminf(c0, c1), d1 = fminf(c2, c3);
        float d2 = fminf(c4, c5), d3 = fminf(c6, t[14]);
        float m2 = fminf(fminf(d0, d1), fminf(d2, d3));

        // sign(0)=0 kills the whole row  <=>  m1 == 0
        const float zal = (m1 == 0.0f) ? 0.0f : alv[it];
        const float m1c = fmaxf(0.0f, m1 - bev[it]) * zal;
        const float m2c = fmaxf(0.0f, m2 - bev[it]) * zal;

        #pragma unroll
        for (int j = 0; j < ROW_DEG; ++j) {
            float mag = (j == j1) ? m2c : m1c;
            unsigned sb = (px ^ __float_as_uint(Mv[j])) & 0x80000000u;
            float Ej = __uint_as_float(__float_as_uint(mag) ^ sb);
            Ev[j] = Ej;
            E_cm[ebase + sl[j]] = Ej;
        }
        __syncthreads();

        // ── variable-node phase: 4 columns/thread, 4x LDS.128 each ──
        const int nxt = cur ^ 1;
        #pragma unroll
        for (int k = 0; k < NV / MROWS; ++k) {
            int c = row + k * MROWS;
            const float4* p = (const float4*)(E_cm + ebase + c * MAXD);
            float4 x = p[0], y = p[1], u = p[2], w = p[3];
            float ssum = ((x.x + x.y) + (x.z + x.w)) + ((y.x + y.y) + (y.z + y.w))
                       + ((u.x + u.y) + (u.z + u.w)) + ((w.x + w.y) + (w.z + w.w));
            float cs = r_s[half * NV + c] + ssum;
            if (it == ITERS - 1)
                out[b * NV + c] = cs;
            else
                sE[nxt * BPC * NV + half * NV + c] = cs;
        }
        if (it != ITERS - 1) __syncthreads();
        cur = nxt;
    }
}

extern "C" void kernel_launch(void* const* d_in, const int* in_sizes, int n_in,
                              void* d_out, int out_size)
{
    const float* r     = (const float*)d_in[0];   // [256, 576]
    const float* H     = (const float*)d_in[1];   // [144, 576]
    const float* alpha = (const float*)d_in[2];   // [3]
    const float* beta  = (const float*)d_in[3];   // [3]
    float* out = (float*)d_out;                   // [256, 576]

    const int smem = (3 * BPC * NV + BPC * NV * MAXD) * sizeof(float);  // ~87.6 KB
    cudaFuncSetAttribute(ldpc_kernel, cudaFuncAttributeMaxDynamicSharedMemorySize, smem);

    prep_kernel<<<MROWS, NV>>>(H);
    ldpc_kernel<<<BATCH / BPC, THREADS, smem>>>(r, alpha, beta, out);
}

// round 6
// speedup vs baseline: 2.6291x; 1.1805x over previous
#include <cuda_runtime.h>

#define NV 576
#define MROWS 144
#define ROW_DEG 15
#define BATCH 256
#define ITERS 3
#define THREADS MROWS              // 144: one thread per check row
#define MAXD 16                    // padded max column degree
#define COLS_PT (NV / MROWS)       // 4 columns per thread

// Packed per-edge descriptor: (E_cm offset << 16) | column. Row-padded to 16
// entries (64B) so the decoder loads each row's edges with 4x LDG.128.
__device__ int g_edge[MROWS * 16];
// Monotone per-column counters for slot assignment. Never reset: (s + c) & 15
// stays distinct within a column for any base as long as degree <= 16.
__device__ unsigned g_cnt[NV];

// One CTA per check row, one thread per column: single parallel LDG round,
// ballot + cross-warp prefix -> edge position j (columns ascending, matching
// top_k's lowest-index tie-break), then a global atomic gives the column slot.
__global__ __launch_bounds__(NV) void prep_kernel(const float* __restrict__ H) {
    __shared__ int wcnt[NV / 32];
    const int m = blockIdx.x;
    const int t = threadIdx.x;
    const int lane = t & 31;
    const int w = t >> 5;

    float v = H[m * NV + t];
    unsigned ball = __ballot_sync(0xffffffffu, v != 0.0f);
    if (lane == 0) wcnt[w] = __popc(ball);
    __syncthreads();

    int pre = __popc(ball & ((1u << lane) - 1u));
    #pragma unroll
    for (int k = 0; k < NV / 32; ++k)
        pre += (k < w) ? wcnt[k] : 0;

    if (v != 0.0f) {
        unsigned s = atomicAdd(&g_cnt[t], 1u);
        int se = (int)((s + (unsigned)t) & (MAXD - 1u));
        int off = t * MAXD + se;                 // < 9216, fits in 16 bits
        g_edge[m * 16 + pre] = (off << 16) | t;
    }
}

__global__ __launch_bounds__(THREADS) void ldpc_kernel(
    const float* __restrict__ r,
    const float* __restrict__ alpha,
    const float* __restrict__ beta,
    float* __restrict__ out)
{
    extern __shared__ float sm[];
    float* r_s  = sm;                     // [NV]
    float* sE   = sm + NV;                // [2][NV] ping-pong: r + col sums of E
    float* E_cm = sm + 3 * NV;            // [NV*MAXD] column-major padded E

    const int row = threadIdx.x;
    const int b   = blockIdx.x;

    float alv[ITERS], bev[ITERS];
    #pragma unroll
    for (int k = 0; k < ITERS; ++k) { alv[k] = alpha[k]; bev[k] = beta[k]; }

    // Zero E_cm once (pads stay 0; live slots rewritten each iteration)
    float4* ez = (float4*)E_cm;
    #pragma unroll
    for (int i = row; i < NV * MAXD / 4; i += THREADS)
        ez[i] = make_float4(0.f, 0.f, 0.f, 0.f);

    const float* rb = r + b * NV;
    #pragma unroll
    for (int k = 0; k < COLS_PT; ++k) {
        int i = row + k * MROWS;
        float v = rb[i];
        r_s[i] = v;
        sE[i]  = v;
    }

    // Packed edges: 4x LDG.128
    int cc[ROW_DEG], sl[ROW_DEG];
    {
        const int4* ep = (const int4*)(g_edge + row * 16);
        int e[16];
        #pragma unroll
        for (int q = 0; q < 4; ++q) {
            int4 x = ep[q];
            e[q * 4 + 0] = x.x; e[q * 4 + 1] = x.y;
            e[q * 4 + 2] = x.z; e[q * 4 + 3] = x.w;
        }
        #pragma unroll
        for (int j = 0; j < ROW_DEG; ++j) {
            cc[j] = e[j] & 0xFFFF;
            sl[j] = ((unsigned)e[j]) >> 16;
        }
    }

    float Ev[ROW_DEG];
    #pragma unroll
    for (int j = 0; j < ROW_DEG; ++j) Ev[j] = 0.0f;

    __syncthreads();

    int cur = 0;

    #pragma unroll
    for (int it = 0; it < ITERS; ++it) {
        // ── check-node phase ──
        float Mv[ROW_DEG];
        const float* sEc = sE + cur * NV;
        #pragma unroll
        for (int j = 0; j < ROW_DEG; ++j)
            Mv[j] = sEc[cc[j]] - Ev[j];          // r + sumE - E_j

        // sign parity: XOR of sign bits (parallel LOP tree)
        unsigned px = 0u;
        #pragma unroll
        for (int j = 0; j < ROW_DEG; ++j) px ^= __float_as_uint(Mv[j]);
        px &= 0x80000000u;

        // min1 via FMNMX tree over |Mv|
        float a0 = fminf(fabsf(Mv[0]),  fabsf(Mv[1]));
        float a1 = fminf(fabsf(Mv[2]),  fabsf(Mv[3]));
        float a2 = fminf(fabsf(Mv[4]),  fabsf(Mv[5]));
        float a3 = fminf(fabsf(Mv[6]),  fabsf(Mv[7]));
        float a4 = fminf(fabsf(Mv[8]),  fabsf(Mv[9]));
        float a5 = fminf(fabsf(Mv[10]), fabsf(Mv[11]));
        float a6 = fminf(fabsf(Mv[12]), fabsf(Mv[13]));
        float b0 = fminf(a0, a1), b1 = fminf(a2, a3);
        float b2 = fminf(a4, a5), b3 = fminf(a6, fabsf(Mv[14]));
        float m1 = fminf(fminf(b0, b1), fminf(b2, b3));

        // j1 = lowest index achieving min1
        unsigned msk = 0u;
        #pragma unroll
        for (int j = 0; j < ROW_DEG; ++j)
            msk |= (fabsf(Mv[j]) == m1) ? (1u << j) : 0u;
        const int j1 = __ffs(msk) - 1;

        // min2 = min over j != j1
        float t[ROW_DEG];
        #pragma unroll
        for (int j = 0; j < ROW_DEG; ++j)
            t[j] = (j == j1) ? 3.4e38f : fabsf(Mv[j]);
        float c0 = fminf(t[0], t[1]),  c1 = fminf(t[2], t[3]);
        float c2 = fminf(t[4], t[5]),  c3 = fminf(t[6], t[7]);
        float c4 = fminf(t[8], t[9]),  c5 = fminf(t[10], t[11]);
        float c6 = fminf(t[12], t[13]);
        float d0 = fminf(c0, c1), d1 = fminf(c2, c3);
        float d2 = fminf(c4, c5), d3 = fminf(c6, t[14]);
        float m2 = fminf(fminf(d0, d1), fminf(d2, d3));

        // sign(0)=0 kills the whole row  <=>  m1 == 0
        const float zal = (m1 == 0.0f) ? 0.0f : alv[it];
        const float m1c = fmaxf(0.0f, m1 - bev[it]) * zal;
        const float m2c = fmaxf(0.0f, m2 - bev[it]) * zal;

        #pragma unroll
        for (int j = 0; j < ROW_DEG; ++j) {
            float mag = (j == j1) ? m2c : m1c;
            unsigned sb = (px ^ __float_as_uint(Mv[j])) & 0x80000000u;
            float Ej = __uint_as_float(__float_as_uint(mag) ^ sb);
            Ev[j] = Ej;
            E_cm[sl[j]] = Ej;
        }
        __syncthreads();

        // ── variable-node phase: 4 columns/thread, 4x LDS.128 each ──
        const int nxt = cur ^ 1;
        #pragma unroll
        for (int k = 0; k < COLS_PT; ++k) {
            int c = row + k * MROWS;
            const float4* p = (const float4*)(E_cm + c * MAXD);
            float4 x = p[0], y = p[1], u = p[2], w = p[3];
            float ssum = ((x.x + x.y) + (x.z + x.w)) + ((y.x + y.y) + (y.z + y.w))
                       + ((u.x + u.y) + (u.z + u.w)) + ((w.x + w.y) + (w.z + w.w));
            float cs = r_s[c] + ssum;
            if (it == ITERS - 1)
                out[b * NV + c] = cs;
            else
                sE[nxt * NV + c] = cs;
        }
        if (it != ITERS - 1) __syncthreads();
        cur = nxt;
    }
}

extern "C" void kernel_launch(void* const* d_in, const int* in_sizes, int n_in,
                              void* d_out, int out_size)
{
    const float* r     = (const float*)d_in[0];   // [256, 576]
    const float* H     = (const float*)d_in[1];   // [144, 576]
    const float* alpha = (const float*)d_in[2];   // [3]
    const float* beta  = (const float*)d_in[3];   // [3]
    float* out = (float*)d_out;                   // [256, 576]

    const int smem = (3 * NV + NV * MAXD) * sizeof(float);  // 43.8 KB -> 2 CTAs/SM
    cudaFuncSetAttribute(ldpc_kernel, cudaFuncAttributeMaxDynamicSharedMemorySize, smem);

    prep_kernel<<<MROWS, NV>>>(H);
    ldpc_kernel<<<BATCH, THREADS, smem>>>(r, alpha, beta, out);
}

// round 7
// speedup vs baseline: 3.1220x; 1.1875x over previous
#include <cuda_runtime.h>

#define NV 576
#define MROWS 144
#define ROW_DEG 15
#define BATCH 256
#define ITERS 3
#define THREADS MROWS              // 144: one thread per check row
#define MAXD 16                    // padded max column degree (slot range)
#define CSTRIDE 20                 // E_cm column stride in floats (80B) -> conflict-free LDS.128
#define COLS_PT (NV / MROWS)       // 4 columns per thread

// Packed per-edge descriptor: (E_cm offset << 16) | column. Row-padded to 16
// entries (64B) so the decoder loads each row's edges with 4x LDG.128.
__device__ int g_edge[MROWS * 16];
// Monotone per-column counters for slot assignment. Never reset: (s + c) & 15
// stays distinct within a column for any base as long as degree <= 16.
__device__ unsigned g_cnt[NV];

// One CTA per check row, one thread per column: single parallel LDG round,
// ballot + cross-warp prefix -> edge position j (columns ascending, matching
// top_k's lowest-index tie-break), then a global atomic gives the column slot.
__global__ __launch_bounds__(NV) void prep_kernel(const float* __restrict__ H) {
    __shared__ int wcnt[NV / 32];
    const int m = blockIdx.x;
    const int t = threadIdx.x;
    const int lane = t & 31;
    const int w = t >> 5;

    float v = H[m * NV + t];
    unsigned ball = __ballot_sync(0xffffffffu, v != 0.0f);
    if (lane == 0) wcnt[w] = __popc(ball);
    __syncthreads();

    int pre = __popc(ball & ((1u << lane) - 1u));
    #pragma unroll
    for (int k = 0; k < NV / 32; ++k)
        pre += (k < w) ? wcnt[k] : 0;

    if (v != 0.0f) {
        unsigned s = atomicAdd(&g_cnt[t], 1u);
        int se = (int)((s + (unsigned)t) & (MAXD - 1u));
        int off = t * CSTRIDE + se;              // < 11520, fits in 16 bits
        g_edge[m * 16 + pre] = (off << 16) | t;
    }
}

__global__ __launch_bounds__(THREADS) void ldpc_kernel(
    const float* __restrict__ r,
    const float* __restrict__ alpha,
    const float* __restrict__ beta,
    float* __restrict__ out)
{
    extern __shared__ float sm[];
    float* r_s  = sm;                     // [NV]
    float* sE   = sm + NV;                // [2][NV] ping-pong: r + col sums of E
    float* E_cm = sm + 3 * NV;            // [NV*CSTRIDE] column-major padded E

    const int row = threadIdx.x;
    const int b   = blockIdx.x;

    // ---- prefetch all global loads first (overlap DRAM latency with init STS) ----
    const int4* ep = (const int4*)(g_edge + row * 16);
    int4 e0 = ep[0], e1 = ep[1], e2 = ep[2], e3 = ep[3];

    const float* rb = r + b * NV;
    float rv[COLS_PT];
    #pragma unroll
    for (int k = 0; k < COLS_PT; ++k)
        rv[k] = rb[row + k * MROWS];

    float alv[ITERS], bev[ITERS];
    #pragma unroll
    for (int k = 0; k < ITERS; ++k) { alv[k] = alpha[k]; bev[k] = beta[k]; }

    // Zero E_cm once (pads stay 0; live slots rewritten each iteration)
    float4* ez = (float4*)E_cm;
    #pragma unroll
    for (int i = row; i < NV * CSTRIDE / 4; i += THREADS)
        ez[i] = make_float4(0.f, 0.f, 0.f, 0.f);

    #pragma unroll
    for (int k = 0; k < COLS_PT; ++k) {
        int i = row + k * MROWS;
        r_s[i] = rv[k];
        sE[i]  = rv[k];
    }

    int cc[ROW_DEG], sl[ROW_DEG];
    {
        int e[16] = { e0.x, e0.y, e0.z, e0.w, e1.x, e1.y, e1.z, e1.w,
                      e2.x, e2.y, e2.z, e2.w, e3.x, e3.y, e3.z, e3.w };
        #pragma unroll
        for (int j = 0; j < ROW_DEG; ++j) {
            cc[j] = e[j] & 0xFFFF;
            sl[j] = ((unsigned)e[j]) >> 16;
        }
    }

    float Ev[ROW_DEG];
    #pragma unroll
    for (int j = 0; j < ROW_DEG; ++j) Ev[j] = 0.0f;

    __syncthreads();

    int cur = 0;

    #pragma unroll
    for (int it = 0; it < ITERS; ++it) {
        // ── check-node phase ──
        float Mv[ROW_DEG];
        const float* sEc = sE + cur * NV;
        #pragma unroll
        for (int j = 0; j < ROW_DEG; ++j)
            Mv[j] = sEc[cc[j]] - Ev[j];          // r + sumE - E_j

        // sign parity: XOR of sign bits (parallel LOP tree)
        unsigned px = 0u;
        #pragma unroll
        for (int j = 0; j < ROW_DEG; ++j) px ^= __float_as_uint(Mv[j]);
        px &= 0x80000000u;

        // min1 via FMNMX tree over |Mv|
        float a0 = fminf(fabsf(Mv[0]),  fabsf(Mv[1]));
        float a1 = fminf(fabsf(Mv[2]),  fabsf(Mv[3]));
        float a2 = fminf(fabsf(Mv[4]),  fabsf(Mv[5]));
        float a3 = fminf(fabsf(Mv[6]),  fabsf(Mv[7]));
        float a4 = fminf(fabsf(Mv[8]),  fabsf(Mv[9]));
        float a5 = fminf(fabsf(Mv[10]), fabsf(Mv[11]));
        float a6 = fminf(fabsf(Mv[12]), fabsf(Mv[13]));
        float b0 = fminf(a0, a1), b1 = fminf(a2, a3);
        float b2 = fminf(a4, a5), b3 = fminf(a6, fabsf(Mv[14]));
        float m1 = fminf(fminf(b0, b1), fminf(b2, b3));

        // j1 = lowest index achieving min1
        unsigned msk = 0u;
        #pragma unroll
        for (int j = 0; j < ROW_DEG; ++j)
            msk |= (fabsf(Mv[j]) == m1) ? (1u << j) : 0u;
        const int j1 = __ffs(msk) - 1;

        // min2 = min over j != j1
        float t[ROW_DEG];
        #pragma unroll
        for (int j = 0; j < ROW_DEG; ++j)
            t[j] = (j == j1) ? 3.4e38f : fabsf(Mv[j]);
        float c0 = fminf(t[0], t[1]),  c1 = fminf(t[2], t[3]);
        float c2 = fminf(t[4], t[5]),  c3 = fminf(t[6], t[7]);
        float c4 = fminf(t[8], t[9]),  c5 = fminf(t[10], t[11]);
        float c6 = fminf(t[12], t[13]);
        float d0 = fminf(c0, c1), d1 = fminf(c2, c3);
        float d2 = fminf(c4, c5), d3 = fminf(c6, t[14]);
        float m2 = fminf(fminf(d0, d1), fminf(d2, d3));

        // sign(0)=0 kills the whole row  <=>  m1 == 0
        const float zal = (m1 == 0.0f) ? 0.0f : alv[it];
        const float m1c = fmaxf(0.0f, m1 - bev[it]) * zal;
        const float m2c = fmaxf(0.0f, m2 - bev[it]) * zal;

        #pragma unroll
        for (int j = 0; j < ROW_DEG; ++j) {
            float mag = (j == j1) ? m2c : m1c;
            unsigned sb = (px ^ __float_as_uint(Mv[j])) & 0x80000000u;
            float Ej = __uint_as_float(__float_as_uint(mag) ^ sb);
            Ev[j] = Ej;
            E_cm[sl[j]] = Ej;
        }
        __syncthreads();

        // ── variable-node phase: 4 columns/thread, 4x LDS.128 each, conflict-free ──
        const int nxt = cur ^ 1;
        #pragma unroll
        for (int k = 0; k < COLS_PT; ++k) {
            int c = row + k * MROWS;
            const float4* p = (const float4*)(E_cm + c * CSTRIDE);
            float4 x = p[0], y = p[1], u = p[2], w = p[3];
            float ssum = ((x.x + x.y) + (x.z + x.w)) + ((y.x + y.y) + (y.z + y.w))
                       + ((u.x + u.y) + (u.z + u.w)) + ((w.x + w.y) + (w.z + w.w));
            float cs = r_s[c] + ssum;
            if (it == ITERS - 1)
                out[b * NV + c] = cs;
            else
                sE[nxt * NV + c] = cs;
        }
        if (it != ITERS - 1) __syncthreads();
        cur = nxt;
    }
}

extern "C" void kernel_launch(void* const* d_in, const int* in_sizes, int n_in,
                              void* d_out, int out_size)
{
    const float* r     = (const float*)d_in[0];   // [256, 576]
    const float* H     = (const float*)d_in[1];   // [144, 576]
    const float* alpha = (const float*)d_in[2];   // [3]
    const float* beta  = (const float*)d_in[3];   // [3]
    float* out = (float*)d_out;                   // [256, 576]

    const int smem = (3 * NV + NV * CSTRIDE) * sizeof(float);  // ~53 KB -> 2 CTAs/SM
    cudaFuncSetAttribute(ldpc_kernel, cudaFuncAttributeMaxDynamicSharedMemorySize, smem);

    prep_kernel<<<MROWS, NV>>>(H);
    ldpc_kernel<<<BATCH, THREADS, smem>>>(r, alpha, beta, out);
}

// round 8
// speedup vs baseline: 3.1313x; 1.0030x over previous
#include <cuda_runtime.h>

#define NV 576
#define MROWS 144
#define ROW_DEG 15
#define BATCH 256
#define ITERS 3
#define THREADS (2 * MROWS)        // 288: two threads per check row
#define MAXD 16                    // padded max column degree (slot range)
#define CSTRIDE 20                 // E_cm column stride in floats (80B) -> conflict-free LDS.128
#define COLS_PT (NV / THREADS)     // 2 columns per thread
#define FBIG 3.4e38f

// Packed per-edge descriptor: (E_cm offset << 16) | column. Row-padded to 16
// entries (64B); each half-row thread loads its 8 with 2x LDG.128.
__device__ int g_edge[MROWS * 16];
// Monotone per-column counters for slot assignment. Never reset: (s + c) & 15
// stays distinct within a column for any base as long as degree <= 16.
__device__ unsigned g_cnt[NV];

// One CTA per check row, one thread per column: single parallel LDG round,
// ballot + cross-warp prefix -> edge position (columns ascending, matching
// top_k's lowest-index tie-break), then a global atomic gives the column slot.
__global__ __launch_bounds__(NV) void prep_kernel(const float* __restrict__ H) {
    __shared__ int wcnt[NV / 32];
    const int m = blockIdx.x;
    const int t = threadIdx.x;
    const int lane = t & 31;
    const int w = t >> 5;

    float v = H[m * NV + t];
    unsigned ball = __ballot_sync(0xffffffffu, v != 0.0f);
    if (lane == 0) wcnt[w] = __popc(ball);
    __syncthreads();

    int pre = __popc(ball & ((1u << lane) - 1u));
    #pragma unroll
    for (int k = 0; k < NV / 32; ++k)
        pre += (k < w) ? wcnt[k] : 0;

    if (v != 0.0f) {
        unsigned s = atomicAdd(&g_cnt[t], 1u);
        int se = (int)((s + (unsigned)t) & (MAXD - 1u));
        int off = t * CSTRIDE + se;              // < 11520, fits in 16 bits
        g_edge[m * 16 + pre] = (off << 16) | t;
    }
}

__global__ __launch_bounds__(THREADS) void ldpc_kernel(
    const float* __restrict__ r,
    const float* __restrict__ alpha,
    const float* __restrict__ beta,
    float* __restrict__ out)
{
    extern __shared__ float sm[];
    float* r_s  = sm;                     // [NV]
    float* sE   = sm + NV;                // [2][NV] ping-pong: r + col sums of E
    float* E_cm = sm + 3 * NV;            // [NV*CSTRIDE] column-major padded E

    const int tid  = threadIdx.x;
    const int row  = tid >> 1;
    const int part = tid & 1;             // 0: edges 0-7, 1: edges 8-14
    const int b    = blockIdx.x;
    const int nloc = 8 - part;            // live local edges (8 or 7)
    const int jgb  = part * 8;            // global index base

    // ---- prefetch global loads (overlap DRAM latency with init STS) ----
    const int4* ep = (const int4*)(g_edge + row * 16 + part * 8);
    int4 e0 = ep[0], e1 = ep[1];

    const float* rb = r + b * NV;
    float rv[COLS_PT];
    #pragma unroll
    for (int k = 0; k < COLS_PT; ++k)
        rv[k] = rb[tid + k * THREADS];

    float alv[ITERS], bev[ITERS];
    #pragma unroll
    for (int k = 0; k < ITERS; ++k) { alv[k] = alpha[k]; bev[k] = beta[k]; }

    // Zero E_cm once (pads stay 0; live slots rewritten each iteration)
    float4* ez = (float4*)E_cm;
    #pragma unroll
    for (int i = tid; i < NV * CSTRIDE / 4; i += THREADS)
        ez[i] = make_float4(0.f, 0.f, 0.f, 0.f);

    #pragma unroll
    for (int k = 0; k < COLS_PT; ++k) {
        int i = tid + k * THREADS;
        r_s[i] = rv[k];
        sE[i]  = rv[k];
    }

    int cc[8], sl[8];
    {
        int e[8] = { e0.x, e0.y, e0.z, e0.w, e1.x, e1.y, e1.z, e1.w };
        #pragma unroll
        for (int j = 0; j < 8; ++j) {
            cc[j] = e[j] & 0xFFFF;
            sl[j] = ((unsigned)e[j]) >> 16;
        }
    }

    float Ev[8];
    #pragma unroll
    for (int j = 0; j < 8; ++j) Ev[j] = 0.0f;

    __syncthreads();

    int cur = 0;

    #pragma unroll
    for (int it = 0; it < ITERS; ++it) {
        // ── check-node phase: each thread scans its <=8 edges ──
        float Mv[8];
        const float* sEc = sE + cur * NV;
        #pragma unroll
        for (int j = 0; j < 8; ++j)
            Mv[j] = sEc[cc[j]] - Ev[j];          // r + sumE - E_j
        if (part) Mv[7] = FBIG;                  // dummy edge: +big, sign 0, never min

        // local sign parity (dummy is positive -> no contribution)
        unsigned px = 0u;
        #pragma unroll
        for (int j = 0; j < 8; ++j) px ^= __float_as_uint(Mv[j]);

        // local min1 via FMNMX tree over |Mv|
        float a0 = fminf(fabsf(Mv[0]), fabsf(Mv[1]));
        float a1 = fminf(fabsf(Mv[2]), fabsf(Mv[3]));
        float a2 = fminf(fabsf(Mv[4]), fabsf(Mv[5]));
        float a3 = fminf(fabsf(Mv[6]), fabsf(Mv[7]));
        float m1l = fminf(fminf(a0, a1), fminf(a2, a3));

        // local argmin (lowest local index)
        unsigned msk = 0u;
        #pragma unroll
        for (int j = 0; j < 8; ++j)
            msk |= (fabsf(Mv[j]) == m1l) ? (1u << j) : 0u;
        const int j1l = __ffs(msk) - 1;

        // local min2 (mask local argmin)
        float t[8];
        #pragma unroll
        for (int j = 0; j < 8; ++j)
            t[j] = (j == j1l) ? FBIG : fabsf(Mv[j]);
        float c0 = fminf(t[0], t[1]), c1 = fminf(t[2], t[3]);
        float c2 = fminf(t[4], t[5]), c3 = fminf(t[6], t[7]);
        float m2l = fminf(fminf(c0, c1), fminf(c2, c3));

        const int j1g = j1l + jgb;               // global edge index

        // ── merge with partner lane (lane^1, same warp) ──
        float m1o = __shfl_xor_sync(0xffffffffu, m1l, 1);
        float m2o = __shfl_xor_sync(0xffffffffu, m2l, 1);
        int   j1o = __shfl_xor_sync(0xffffffffu, j1g, 1);
        unsigned pxo = __shfl_xor_sync(0xffffffffu, px, 1);
        const unsigned pxt = (px ^ pxo) & 0x80000000u;

        // all part-0 indices < part-1 indices, so value tie -> lower j wins
        const bool ow = (m1o < m1l) || (m1o == m1l && j1o < j1g);
        const float M1 = ow ? m1o : m1l;
        const int   J1 = ow ? j1o : j1g;
        const float M2 = fminf(ow ? m2o : m2l, ow ? m1l : m1o);

        // sign(0)=0 kills the whole row  <=>  M1 == 0
        const float zal = (M1 == 0.0f) ? 0.0f : alv[it];
        const float m1c = fmaxf(0.0f, M1 - bev[it]) * zal;
        const float m2c = fmaxf(0.0f, M2 - bev[it]) * zal;

        #pragma unroll
        for (int j = 0; j < 8; ++j) {
            float mag = ((j + jgb) == J1) ? m2c : m1c;
            unsigned sb = (pxt ^ __float_as_uint(Mv[j])) & 0x80000000u;
            float Ej = __uint_as_float(__float_as_uint(mag) ^ sb);
            Ev[j] = Ej;
            if (j < nloc) E_cm[sl[j]] = Ej;      // skip dummy store
        }
        __syncthreads();

        // ── variable-node phase: 2 columns/thread, 4x LDS.128 each, conflict-free ──
        const int nxt = cur ^ 1;
        #pragma unroll
        for (int k = 0; k < COLS_PT; ++k) {
            int c = tid + k * THREADS;
            const float4* p = (const float4*)(E_cm + c * CSTRIDE);
            float4 x = p[0], y = p[1], u = p[2], w = p[3];
            float ssum = ((x.x + x.y) + (x.z + x.w)) + ((y.x + y.y) + (y.z + y.w))
                       + ((u.x + u.y) + (u.z + u.w)) + ((w.x + w.y) + (w.z + w.w));
            float cs = r_s[c] + ssum;
            if (it == ITERS - 1)
                out[b * NV + c] = cs;
            else
                sE[nxt * NV + c] = cs;
        }
        if (it != ITERS - 1) __syncthreads();
        cur = nxt;
    }
}

extern "C" void kernel_launch(void* const* d_in, const int* in_sizes, int n_in,
                              void* d_out, int out_size)
{
    const float* r     = (const float*)d_in[0];   // [256, 576]
    const float* H     = (const float*)d_in[1];   // [144, 576]
    const float* alpha = (const float*)d_in[2];   // [3]
    const float* beta  = (const float*)d_in[3];   // [3]
    float* out = (float*)d_out;                   // [256, 576]

    const int smem = (3 * NV + NV * CSTRIDE) * sizeof(float);  // ~53 KB -> 2 CTAs/SM
    cudaFuncSetAttribute(ldpc_kernel, cudaFuncAttributeMaxDynamicSharedMemorySize, smem);

    prep_kernel<<<MROWS, NV>>>(H);
    ldpc_kernel<<<BATCH, THREADS, smem>>>(r, alpha, beta, out);
}